// round 15
// baseline (speedup 1.0000x reference)
#include <cuda_runtime.h>
#include <cuda_bf16.h>
#include <cuda_fp16.h>
#include <math.h>
#include <stdint.h>

#define BATCH 64
#define TSEQ  2048
#define UNITS 512
#define EMB   256
#define ROWS  (BATCH * TSEQ)   // 131072

#define BSCALE 64.0f           // Wa pre-scale into e4m3 range
#define INV_BS (1.0f / 64.0f)

// ------------------------- device scratch ----------------------------------
__device__ float g_x[BATCH * UNITS];
__device__ float g_xg[BATCH * 3 * UNITS];
__device__ float g_qplus[BATCH * UNITS];
__device__ float g_reczr[BATCH * 2 * UNITS];
__device__ float g_score[ROWS];
__device__ float g_attn[BATCH * TSEQ];
__device__ float g_partial[BATCH * 16 * UNITS];
__device__ float g_ctxvec[BATCH * UNITS];
__device__ float g_z[BATCH * UNITS];
__device__ float g_rh[BATCH * UNITS];
__device__ float g_h[BATCH * UNITS];
__device__ float g_gp[1048576];            // split-K partials (4MB)
__device__ uint32_t g_WaQ[65536];          // Wa e4m3, B-fragment order

// partial regions inside g_gp for the merged pre-score GEMMs
#define GP_X  0          // [4][64][512]
#define GP_Q  131072     // [8][64][512]
#define GP_R  393216     // [8][64][1024]
#define GP_H  786432     // [8][64][512]  rec_h partials (disjoint from cg base)

// ------------------------- helpers -----------------------------------------
__device__ __forceinline__ void cp16(void* dst_smem, const void* src) {
    uint32_t d = (uint32_t)__cvta_generic_to_shared(dst_smem);
    asm volatile("cp.async.cg.shared.global [%0], [%1], 16;\n" :: "r"(d), "l"(src));
}
#define CP_COMMIT() asm volatile("cp.async.commit_group;\n" ::)
#define CP_WAIT0()  asm volatile("cp.async.wait_group 0;\n" ::)

__device__ __forceinline__ float tanh_approx(float x) {
    float y;
    asm("tanh.approx.f32 %0, %1;" : "=f"(y) : "f"(x));
    return y;
}

// pack 4 floats (k-ascending) into 4 e4m3 bytes
__device__ __forceinline__ uint32_t pack_e4m3(float4 v) {
    uint16_t lo, hi;
    asm("cvt.rn.satfinite.e4m3x2.f32 %0, %1, %2;" : "=h"(lo) : "f"(v.y), "f"(v.x));
    asm("cvt.rn.satfinite.e4m3x2.f32 %0, %1, %2;" : "=h"(hi) : "f"(v.w), "f"(v.z));
    uint32_t r;
    asm("mov.b32 %0, {%1, %2};" : "=r"(r) : "h"(lo), "h"(hi));
    return r;
}

// fp8 MMA with f16 accumulators (2-reg D)
__device__ __forceinline__ void mma_fp8_h(uint32_t* d, const uint32_t* a,
                                          uint32_t b0, uint32_t b1) {
    asm volatile(
        "mma.sync.aligned.m16n8k32.row.col.f16.e4m3.e4m3.f16 "
        "{%0,%1}, {%2,%3,%4,%5}, {%6,%7}, {%0,%1};\n"
        : "+r"(d[0]), "+r"(d[1])
        : "r"(a[0]), "r"(a[1]), "r"(a[2]), "r"(a[3]), "r"(b0), "r"(b1)
        : "memory");
}

// ------------------------- prep: Wa -> e4m3 B-fragment layout ---------------
// dst u32 index [(kt*64 + nb_global)*32 + lane]*4 + w  (layout proven R10/R11)
__global__ void prep_waq_kernel(const float* __restrict__ Wa,
                                uint32_t* __restrict__ dst) {
    __shared__ float s[64][65];
    int kt = blockIdx.x >> 3;
    int nbg = blockIdx.x & 7;
    int k0 = kt * 64, n0 = nbg * 64;
    int tid = threadIdx.x;              // 256
#pragma unroll
    for (int i = 0; i < 16; i++) {
        int idx = tid + i * 256;
        int kl = idx >> 6, nl = idx & 63;
        s[kl][nl] = Wa[(k0 + kl) * UNITS + n0 + nl];
    }
    __syncthreads();
#pragma unroll
    for (int j = 0; j < 4; j++) {
        int wi = tid + j * 256;
        int nb_l = wi >> 7;
        int rem = wi & 127;
        int lane = rem >> 2, w = rem & 3;
        int n_l = nb_l * 8 + (lane >> 2);
        int kb = ((w & 1) ? 16 : 0) + ((w & 2) ? 32 : 0) + (lane & 3) * 4;
        float4 v = make_float4(s[kb][n_l] * BSCALE, s[kb + 1][n_l] * BSCALE,
                               s[kb + 2][n_l] * BSCALE, s[kb + 3][n_l] * BSCALE);
        dst[((kt * 64 + nbg * 8 + nb_l) * 32 + lane) * 4 + w] = pack_e4m3(v);
    }
}

// ------------------------- shared 64x64 GEMM body ---------------------------
__device__ __forceinline__ void gemm64_body(
    float (*As_t)[68], float (*Bs)[68],
    const float* __restrict__ A, int lda,
    const float* __restrict__ B, int ldb, int bcol0,
    int k0, int Kc, float* __restrict__ P, int N, int outn, int prow0) {
    int tid = threadIdx.x;
    int tx = tid & 15, ty = tid >> 4;
    float acc[4][4];
#pragma unroll
    for (int i = 0; i < 4; i++)
#pragma unroll
        for (int j = 0; j < 4; j++) acc[i][j] = 0.f;

    int am = tid >> 2, aj = tid & 3;
    int bk = tid >> 4, bf = tid & 15;

    for (int kb = 0; kb < Kc; kb += 16) {
        float4 av = *(const float4*)&A[am * lda + k0 + kb + aj * 4];
        float4 bv = *(const float4*)&B[(size_t)(k0 + kb + bk) * ldb + bcol0 + bf * 4];
        As_t[aj * 4 + 0][am] = av.x;
        As_t[aj * 4 + 1][am] = av.y;
        As_t[aj * 4 + 2][am] = av.z;
        As_t[aj * 4 + 3][am] = av.w;
        *(float4*)&Bs[bk][bf * 4] = bv;
        __syncthreads();
#pragma unroll
        for (int k = 0; k < 16; k++) {
            float4 a = *(const float4*)&As_t[k][ty * 4];
            float4 b = *(const float4*)&Bs[k][tx * 4];
            acc[0][0] = fmaf(a.x, b.x, acc[0][0]);
            acc[0][1] = fmaf(a.x, b.y, acc[0][1]);
            acc[0][2] = fmaf(a.x, b.z, acc[0][2]);
            acc[0][3] = fmaf(a.x, b.w, acc[0][3]);
            acc[1][0] = fmaf(a.y, b.x, acc[1][0]);
            acc[1][1] = fmaf(a.y, b.y, acc[1][1]);
            acc[1][2] = fmaf(a.y, b.z, acc[1][2]);
            acc[1][3] = fmaf(a.y, b.w, acc[1][3]);
            acc[2][0] = fmaf(a.z, b.x, acc[2][0]);
            acc[2][1] = fmaf(a.z, b.y, acc[2][1]);
            acc[2][2] = fmaf(a.z, b.z, acc[2][2]);
            acc[2][3] = fmaf(a.z, b.w, acc[2][3]);
            acc[3][0] = fmaf(a.w, b.x, acc[3][0]);
            acc[3][1] = fmaf(a.w, b.y, acc[3][1]);
            acc[3][2] = fmaf(a.w, b.z, acc[3][2]);
            acc[3][3] = fmaf(a.w, b.w, acc[3][3]);
        }
        __syncthreads();
    }
#pragma unroll
    for (int i = 0; i < 4; i++) {
        float4 r = make_float4(acc[i][0], acc[i][1], acc[i][2], acc[i][3]);
        *(float4*)&P[(size_t)(prow0 + ty * 4 + i) * N + outn + tx * 4] = r;
    }
}

__global__ __launch_bounds__(256)
void gemm64_kernel(const float* __restrict__ A, int lda,
                   const float* __restrict__ B, int ldb, int bcol0,
                   float* __restrict__ P, int N) {
    __shared__ float As_t[16][68];
    __shared__ float Bs[16][68];
    int n0 = blockIdx.x * 64;
    int ks = blockIdx.y;
    gemm64_body(As_t, Bs, A, lda, B, ldb, bcol0 + n0, ks * 64, 64, P, N, n0, ks * 64);
}

// merged pre-score GEMMs: x (32 CTAs), qplus (64), reczr (128) -> 224 CTAs
__global__ __launch_bounds__(256)
void gemm64_multi_kernel(const float* __restrict__ inputs,
                         const float* __restrict__ h_tm1,
                         const float* __restrict__ Wi,
                         const float* __restrict__ Ua,
                         const float* __restrict__ reck,
                         float* __restrict__ gp) {
    __shared__ float As_t[16][68];
    __shared__ float Bs[16][68];
    int bid = blockIdx.x;
    if (bid < 32) {
        int nb = bid & 7, ks = bid >> 3;
        gemm64_body(As_t, Bs, inputs, EMB, Wi, 512, nb * 64, ks * 64, 64,
                    gp + GP_X, 512, nb * 64, ks * 64);
    } else if (bid < 96) {
        int idx = bid - 32;
        int nb = idx & 7, ks = idx >> 3;
        gemm64_body(As_t, Bs, h_tm1, 512, Ua, 512, nb * 64, ks * 64, 64,
                    gp + GP_Q, 512, nb * 64, ks * 64);
    } else {
        int idx = bid - 96;
        int nb = idx & 15, ks = idx >> 4;
        gemm64_body(As_t, Bs, h_tm1, 512, reck, 1536, nb * 64, ks * 64, 64,
                    gp + GP_R, 1024, nb * 64, ks * 64);
    }
}

__global__ void reduce_multi_kernel(const float* __restrict__ gp,
                                    const float* __restrict__ bi,
                                    const float* __restrict__ ba_u,
                                    const float* __restrict__ ba_w,
                                    float* __restrict__ x,
                                    float* __restrict__ qplus,
                                    float* __restrict__ reczr) {
    int idx = blockIdx.x * 256 + threadIdx.x;
    if (idx < 32768) {
        int m = idx >> 9, n = idx & 511;
        float s = 0.f;
#pragma unroll
        for (int ks = 0; ks < 4; ks++) s += gp[GP_X + (size_t)(ks * 64 + m) * 512 + n];
        x[m * 512 + n] = s + bi[n];
    } else if (idx < 65536) {
        int i = idx - 32768;
        int m = i >> 9, n = i & 511;
        float s = 0.f;
#pragma unroll
        for (int ks = 0; ks < 8; ks++) s += gp[GP_Q + (size_t)(ks * 64 + m) * 512 + n];
        qplus[m * 512 + n] = s + ba_u[n] + ba_w[n];
    } else {
        int i = idx - 65536;
        int m = i >> 10, n = i & 1023;
        float s = 0.f;
#pragma unroll
        for (int ks = 0; ks < 8; ks++) s += gp[GP_R + (size_t)(ks * 64 + m) * 1024 + n];
        reczr[m * 1024 + n] = s;
    }
}

__global__ void reduce64_kernel(const float* __restrict__ P, int N, int KS,
                                const float* __restrict__ b1,
                                float* __restrict__ C, int ldc) {
    int m = blockIdx.y;
    int n = blockIdx.x * 256 + threadIdx.x;
    float s = 0.f;
    for (int ks = 0; ks < KS; ks++) s += P[(size_t)(ks * 64 + m) * N + n];
    if (b1) s += b1[n];
    C[m * ldc + n] = s;
}

// ------------------------- fp8 fused score GEMM (f16 accum, BN=512) ---------
// BM=64 rows, BN=512 (full N), K=512 in 8 chunks of 64. 256 threads, grid 2048.
// Staging of chunk k+1 is INTERLEAVED into the nt-loop of chunk k so its issue
// slots hide under the tensor-pipe occupancy of the MMA burst (R13/R14: phase
// serialization capped tensor at ~44%). 1 CTA/SM, no reg cap (R14: 128-reg cap
// spilled and regressed).
__global__ __launch_bounds__(256, 1)
void score_fp8_kernel(const float* __restrict__ context,
                      const uint32_t* __restrict__ WaQ,
                      const float* __restrict__ qplus,
                      const float* __restrict__ Va,
                      float* __restrict__ score) {
    extern __shared__ uint32_t smem[];
    uint32_t* Abuf[2] = {smem, smem + 1024};            // 4KB each
    uint32_t* Bbuf[2] = {smem + 2048, smem + 10240};    // 32KB each

    const int tid = threadIdx.x;
    const int wid = tid >> 5;
    const int lane = tid & 31;
    const int wm = wid >> 2;            // 0..1: 32-row slice
    const int wn = wid & 3;             // 0..3: 128-col slice
    const size_t row0 = (size_t)blockIdx.x * 64;
    const int b = blockIdx.x >> 5;      // 32 CTAs per batch

    const float4* src = (const float4*)(context + row0 * UNITS);

    // per-thread constant staging indices
    const int st_r = tid >> 4;          // A row for this thread's 4 elements
    const int st_f = tid & 15;          // float4 column
    // A-fragment store address components (constant across chunks)
    const int st_m16 = st_r >> 4, st_rr = st_r & 15;
    const int st_ks = st_f >> 3;
    const int st_ln = ((st_r & 7) << 2) + (st_f & 3);
    const int st_w = (st_rr >> 3) + ((st_f & 4) >> 1);

    uint32_t acc[2][16][2];
#pragma unroll
    for (int i = 0; i < 2; i++)
#pragma unroll
        for (int j = 0; j < 16; j++) { acc[i][j][0] = 0u; acc[i][j][1] = 0u; }

    float4 pf[4];

    // ---- prologue: stage tile 0 ----
    {
        const uint32_t* bs = WaQ;
#pragma unroll
        for (int i = 0; i < 8; i++) {
            int idx = tid + i * 256;
            cp16((char*)Bbuf[0] + idx * 16, bs + idx * 4);
        }
        CP_COMMIT();
    }
#pragma unroll
    for (int i = 0; i < 4; i++) {
        int idx = tid + i * 256;
        int r = idx >> 4, f = idx & 15;
        pf[i] = src[(size_t)r * 128 + f];
    }
#pragma unroll
    for (int i = 0; i < 4; i++) {
        int idx = tid + i * 256;
        int r = idx >> 4, f = idx & 15;
        uint32_t q = pack_e4m3(pf[i]);
        int m16 = r >> 4, rr = r & 15;
        int ks = f >> 3;
        int ln = ((r & 7) << 2) + (f & 3);
        int w = (rr >> 3) + ((f & 4) >> 1);
        Abuf[0][(((m16 * 2 + ks) * 32) + ln) * 4 + w] = q;
    }
    CP_WAIT0();
    __syncthreads();

    // ---- main loop over 8 K-chunks, staging interleaved under MMAs ----
    for (int kt = 0; kt < 8; kt++) {
        const int cur = kt & 1, nxt = cur ^ 1;
        const bool more = (kt < 7);
        const uint32_t* As = Abuf[cur];
        const uint32_t* Bs = Bbuf[cur];
        const uint32_t* bsrc = WaQ + (size_t)((kt + 1) * 64) * 128;

        uint32_t a[2][2][4];
#pragma unroll
        for (int mt = 0; mt < 2; mt++)
#pragma unroll
            for (int ks = 0; ks < 2; ks++) {
                uint4 av = *(const uint4*)&As[((((wm * 2 + mt) * 2 + ks) * 32) + lane) * 4];
                a[mt][ks][0] = av.x; a[mt][ks][1] = av.y;
                a[mt][ks][2] = av.z; a[mt][ks][3] = av.w;
            }

#pragma unroll
        for (int nt = 0; nt < 16; nt++) {
            uint4 bv = *(const uint4*)&Bs[(((wn * 16 + nt) * 32) + lane) * 4];
#pragma unroll
            for (int mt = 0; mt < 2; mt++) {
                mma_fp8_h(acc[mt][nt], a[mt][0], bv.x, bv.y);
                mma_fp8_h(acc[mt][nt], a[mt][1], bv.z, bv.w);
            }
            // --- interleaved staging for chunk kt+1 ---
            if (more) {
                if (nt < 8) {
                    int idx = tid + nt * 256;
                    cp16((char*)Bbuf[nxt] + idx * 16, bsrc + idx * 4);
                    if (nt == 7) CP_COMMIT();
                }
                if (nt < 4)
                    pf[nt] = src[(size_t)(st_r + nt * 16) * 128 + (kt + 1) * 16 + st_f];
                if (nt >= 8 && (nt & 1) == 0) {
                    int i = (nt - 8) >> 1;            // 0..3
                    uint32_t q = pack_e4m3(pf[i]);
                    Abuf[nxt][((((st_m16 + i) * 2 + st_ks) * 32) + st_ln) * 4 + st_w] = q;
                }
            }
        }
        if (more) CP_WAIT0();
        __syncthreads();
    }

    // ---- epilogue: dequant -> +qplus -> tanh -> *Va -> FULL row reduce ----
    float* redf = (float*)smem;          // [64][4]
    float* sq = redf + 256;              // [512]
    float* sv = sq + 512;                // [512]
    for (int i = tid; i < 512; i += 256) {
        sq[i] = qplus[b * UNITS + i];
        sv[i] = Va[i];
    }
    __syncthreads();

    float rsum[2][2] = {{0.f, 0.f}, {0.f, 0.f}};
#pragma unroll
    for (int mt = 0; mt < 2; mt++) {
#pragma unroll
        for (int nt = 0; nt < 16; nt++) {
            int n0 = wn * 128 + nt * 8 + (lane & 3) * 2;
            float q0 = sq[n0], q1 = sq[n0 + 1];
            float v0 = sv[n0], v1 = sv[n0 + 1];
            __half2 h0 = *(__half2*)&acc[mt][nt][0];
            __half2 h1 = *(__half2*)&acc[mt][nt][1];
            rsum[mt][0] += tanh_approx(__low2float(h0) * INV_BS + q0) * v0
                         + tanh_approx(__high2float(h0) * INV_BS + q1) * v1;
            rsum[mt][1] += tanh_approx(__low2float(h1) * INV_BS + q0) * v0
                         + tanh_approx(__high2float(h1) * INV_BS + q1) * v1;
        }
    }
#pragma unroll
    for (int mt = 0; mt < 2; mt++) {
#pragma unroll
        for (int lh = 0; lh < 2; lh++) {
            float s = rsum[mt][lh];
            s += __shfl_xor_sync(0xffffffffu, s, 1);
            s += __shfl_xor_sync(0xffffffffu, s, 2);
            if ((lane & 3) == 0) {
                int r = wm * 32 + mt * 16 + (lane >> 2) + lh * 8;
                redf[r * 4 + wn] = s;
            }
        }
    }
    __syncthreads();
    if (tid < 64) {
        float s = redf[tid * 4] + redf[tid * 4 + 1] +
                  redf[tid * 4 + 2] + redf[tid * 4 + 3];
        score[row0 + tid] = s;
    }
}

// ------------------------- softmax over T per batch -------------------------
__global__ void softmax_kernel(const float* __restrict__ sc,
                               float* __restrict__ attn) {
    int b = blockIdx.x;
    int tid = threadIdx.x;
    __shared__ float red[256];
    float v[8];
    float mx = -1e30f;
#pragma unroll
    for (int i = 0; i < 8; i++) {
        float s = sc[b * TSEQ + i * 256 + tid];
        v[i] = s;
        mx = fmaxf(mx, s);
    }
    red[tid] = mx;
    __syncthreads();
    for (int o = 128; o > 0; o >>= 1) {
        if (tid < o) red[tid] = fmaxf(red[tid], red[tid + o]);
        __syncthreads();
    }
    mx = red[0];
    __syncthreads();
    float sum = 0.f;
#pragma unroll
    for (int i = 0; i < 8; i++) {
        v[i] = expf(v[i] - mx);
        sum += v[i];
    }
    red[tid] = sum;
    __syncthreads();
    for (int o = 128; o > 0; o >>= 1) {
        if (tid < o) red[tid] += red[tid + o];
        __syncthreads();
    }
    float inv = 1.f / red[0];
#pragma unroll
    for (int i = 0; i < 8; i++) attn[b * TSEQ + i * 256 + tid] = v[i] * inv;
}

// ------------------------- ctx_vec = sum_t attn * context -------------------
__global__ void ctx_partial_kernel(const float* __restrict__ context,
                                   const float* __restrict__ attn,
                                   float* __restrict__ partial) {
    int b = blockIdx.x, tc = blockIdx.y;
    int tid = threadIdx.x;
    __shared__ float sa[128];
    sa[tid] = attn[b * TSEQ + tc * 128 + tid];
    __syncthreads();
    const float4* ctx4 =
        (const float4*)context + ((size_t)b * TSEQ + tc * 128) * 128;
    float ax = 0.f, ay = 0.f, az = 0.f, aw = 0.f;
#pragma unroll 8
    for (int t = 0; t < 128; t++) {
        float a = sa[t];
        float4 v = ctx4[(size_t)t * 128 + tid];
        ax = fmaf(a, v.x, ax);
        ay = fmaf(a, v.y, ay);
        az = fmaf(a, v.z, az);
        aw = fmaf(a, v.w, aw);
    }
    float4 r = make_float4(ax, ay, az, aw);
    ((float4*)partial)[(size_t)(b * 16 + tc) * 128 + tid] = r;
}

__global__ void ctx_reduce_kernel(const float* __restrict__ partial,
                                  float* __restrict__ ctxvec) {
    int idx = blockIdx.x * 256 + threadIdx.x;
    int b = idx >> 9, u = idx & 511;
    float s = 0.f;
#pragma unroll
    for (int tc = 0; tc < 16; tc++) s += partial[(size_t)(b * 16 + tc) * UNITS + u];
    ctxvec[idx] = s;
}

// ------------------------- gates (reads cg split-K partials) ----------------
__global__ void gate_kernel(const float* __restrict__ gp,
                            const float* __restrict__ xg,
                            const float* __restrict__ reczr,
                            const float* __restrict__ h_tm1,
                            float* __restrict__ zbuf,
                            float* __restrict__ rh) {
    int idx = blockIdx.x * 256 + threadIdx.x;
    int b = idx >> 9, n = idx & 511;
    float cz = 0.f, cr = 0.f;
#pragma unroll
    for (int ks = 0; ks < 8; ks++) {
        cz += gp[(size_t)(ks * 64 + b) * 1536 + n];
        cr += gp[(size_t)(ks * 64 + b) * 1536 + 512 + n];
    }
    float zin = xg[b * 1536 + n] + reczr[b * 1024 + n] + cz;
    float rin = xg[b * 1536 + 512 + n] + reczr[b * 1024 + 512 + n] + cr;
    float z = 1.f / (1.f + expf(-zin));
    float r = 1.f / (1.f + expf(-rin));
    zbuf[idx] = z;
    rh[idx] = r * h_tm1[idx];
}

// ------------------------- h epilogue (rec_h + cg_h partials) ---------------
__global__ void hfinal_reduce_kernel(const float* __restrict__ gp,
                                     const float* __restrict__ xg,
                                     const float* __restrict__ zbuf,
                                     const float* __restrict__ h_tm1,
                                     float* __restrict__ hbuf,
                                     float* __restrict__ outh) {
    int m = blockIdx.y;
    int n = blockIdx.x * 256 + threadIdx.x;
    float rec_h = 0.f, ch = 0.f;
#pragma unroll
    for (int ks = 0; ks < 8; ks++) {
        rec_h += gp[GP_H + (size_t)(ks * 64 + m) * 512 + n];
        ch    += gp[(size_t)(ks * 64 + m) * 1536 + 1024 + n];
    }
    float hb = tanhf(xg[m * 1536 + 1024 + n] + rec_h + ch);
    float z = zbuf[m * UNITS + n];
    float h = z * h_tm1[m * UNITS + n] + (1.f - z) * hb;
    hbuf[m * UNITS + n] = h;
    outh[m * UNITS + n] = h;
}

// ---------------------------------------------------------------------------
extern "C" void kernel_launch(void* const* d_in, const int* in_sizes, int n_in,
                              void* d_out, int out_size) {
    const float* inputs  = (const float*)d_in[0];
    const float* h_tm1   = (const float*)d_in[1];
    const float* context = (const float*)d_in[2];
    const float* Wi      = (const float*)d_in[3];
    const float* bi      = (const float*)d_in[4];
    const float* kern    = (const float*)d_in[5];
    const float* reck    = (const float*)d_in[6];
    const float* attk    = (const float*)d_in[7];
    const float* bias    = (const float*)d_in[8];
    const float* Wa      = (const float*)d_in[9];
    const float* ba_w    = (const float*)d_in[10];
    const float* Ua      = (const float*)d_in[11];
    const float* ba_u    = (const float*)d_in[12];
    const float* Va      = (const float*)d_in[13];
    /* ba_v (d_in[14]) cancels in softmax */
    const float* Wo      = (const float*)d_in[15];
    const float* bo      = (const float*)d_in[16];

    float* out  = (float*)d_out;
    float* outh = out + BATCH * UNITS;

    float *px, *pxg, *pq, *prec, *psc, *pat, *ppar, *pcv, *pz, *prh, *ph, *pgp;
    uint32_t* pwaq;
    void* tmp;
    cudaGetSymbolAddress(&tmp, g_x);         px   = (float*)tmp;
    cudaGetSymbolAddress(&tmp, g_xg);        pxg  = (float*)tmp;
    cudaGetSymbolAddress(&tmp, g_qplus);     pq   = (float*)tmp;
    cudaGetSymbolAddress(&tmp, g_reczr);     prec = (float*)tmp;
    cudaGetSymbolAddress(&tmp, g_score);     psc  = (float*)tmp;
    cudaGetSymbolAddress(&tmp, g_attn);      pat  = (float*)tmp;
    cudaGetSymbolAddress(&tmp, g_partial);   ppar = (float*)tmp;
    cudaGetSymbolAddress(&tmp, g_ctxvec);    pcv  = (float*)tmp;
    cudaGetSymbolAddress(&tmp, g_z);         pz   = (float*)tmp;
    cudaGetSymbolAddress(&tmp, g_rh);        prh  = (float*)tmp;
    cudaGetSymbolAddress(&tmp, g_h);         ph   = (float*)tmp;
    cudaGetSymbolAddress(&tmp, g_gp);        pgp  = (float*)tmp;
    cudaGetSymbolAddress(&tmp, g_WaQ);       pwaq = (uint32_t*)tmp;

    // raise dynamic smem limit for the score kernel (72 KB > 48 KB default)
    cudaFuncSetAttribute((const void*)score_fp8_kernel,
                         cudaFuncAttributeMaxDynamicSharedMemorySize, 73728);

    // 1. Wa -> e4m3 fragment layout (pre-scaled x64)
    prep_waq_kernel<<<64, 256>>>(Wa, pwaq);

    // 2. merged: x = inputs@Wi ; qplus = h_tm1@Ua ; reczr = h_tm1@reck[:,:1024]
    gemm64_multi_kernel<<<224, 256>>>(inputs, h_tm1, Wi, Ua, reck, pgp);
    reduce_multi_kernel<<<512, 256>>>(pgp, bi, ba_u, ba_w, px, pq, prec);

    // 3. fp8 fused score GEMM (f16 accum, interleaved staging) — ncu slot
    score_fp8_kernel<<<2048, 256, 73728>>>(context, pwaq, pq, Va, psc);

    // 4. xg = x @ kernel + bias   (KS=8)
    gemm64_kernel<<<dim3(24, 8), 256>>>(px, 512, kern, 1536, 0, pgp, 1536);
    reduce64_kernel<<<dim3(6, 64), 256>>>(pgp, 1536, 8, bias, pxg, 1536);

    // 5. softmax over T
    softmax_kernel<<<BATCH, 256>>>(psc, pat);
    // 6. ctx_vec = sum_t attn * context
    ctx_partial_kernel<<<dim3(BATCH, 16), 128>>>(context, pat, ppar);
    ctx_reduce_kernel<<<BATCH * UNITS / 256, 256>>>(ppar, pcv);
    // 7. cg partials = ctx_vec @ attention_kernel (KS=8) -> consumed inline
    gemm64_kernel<<<dim3(24, 8), 256>>>(pcv, 512, attk, 1536, 0, pgp, 1536);
    // 8. z, r gates (sum cg partials inline)
    gate_kernel<<<BATCH * UNITS / 256, 256>>>(pgp, pxg, prec, h_tm1, pz, prh);
    // 9. rec_h partials (disjoint region) + h epilogue (sums rec_h + cg_h)
    gemm64_kernel<<<dim3(8, 8), 256>>>(prh, 512, reck, 1536, 1024, pgp + GP_H, 512);
    hfinal_reduce_kernel<<<dim3(2, 64), 256>>>(pgp, pxg, pz, h_tm1, ph, outh);
    // 10. out = h @ Wo + bo (KS=8)
    gemm64_kernel<<<dim3(8, 8), 256>>>(ph, 512, Wo, 512, 0, pgp, 512);
    reduce64_kernel<<<dim3(2, 64), 256>>>(pgp, 512, 8, bo, out, 512);

    (void)in_sizes; (void)n_in; (void)out_size;
}

// round 16
// speedup vs baseline: 1.0466x; 1.0466x over previous
#include <cuda_runtime.h>
#include <cuda_bf16.h>
#include <cuda_fp16.h>
#include <math.h>
#include <stdint.h>

#define BATCH 64
#define TSEQ  2048
#define UNITS 512
#define EMB   256
#define ROWS  (BATCH * TSEQ)   // 131072

#define BSCALE 64.0f           // Wa pre-scale into e4m3 range
#define INV_BS (1.0f / 64.0f)

// ------------------------- device scratch ----------------------------------
__device__ float g_x[BATCH * UNITS];
__device__ float g_xg[BATCH * 3 * UNITS];
__device__ float g_qplus[BATCH * UNITS];
__device__ float g_reczr[BATCH * 2 * UNITS];
__device__ float g_score[ROWS];
__device__ float g_attn[BATCH * TSEQ];
__device__ float g_partial[BATCH * 16 * UNITS];
__device__ float g_ctxvec[BATCH * UNITS];
__device__ float g_z[BATCH * UNITS];
__device__ float g_rh[BATCH * UNITS];
__device__ float g_h[BATCH * UNITS];
__device__ float g_gp[1048576];            // split-K partials (4MB)
__device__ uint32_t g_WaQ[65536];          // Wa e4m3, B-fragment order
__device__ uint32_t g_ctx8[16777216];      // context e4m3, A-fragment order (64MB)

// partial regions inside g_gp for the merged pre-score GEMMs
#define GP_X  0          // [4][64][512]
#define GP_Q  131072     // [8][64][512]
#define GP_R  393216     // [8][64][1024]
#define GP_H  786432     // [8][64][512]  rec_h partials (disjoint from cg base)

// ------------------------- helpers -----------------------------------------
__device__ __forceinline__ void cp16(void* dst_smem, const void* src) {
    uint32_t d = (uint32_t)__cvta_generic_to_shared(dst_smem);
    asm volatile("cp.async.cg.shared.global [%0], [%1], 16;\n" :: "r"(d), "l"(src));
}
#define CP_COMMIT() asm volatile("cp.async.commit_group;\n" ::)
#define CP_WAIT0()  asm volatile("cp.async.wait_group 0;\n" ::)

__device__ __forceinline__ float tanh_approx(float x) {
    float y;
    asm("tanh.approx.f32 %0, %1;" : "=f"(y) : "f"(x));
    return y;
}

// pack 4 floats (k-ascending) into 4 e4m3 bytes
__device__ __forceinline__ uint32_t pack_e4m3(float4 v) {
    uint16_t lo, hi;
    asm("cvt.rn.satfinite.e4m3x2.f32 %0, %1, %2;" : "=h"(lo) : "f"(v.y), "f"(v.x));
    asm("cvt.rn.satfinite.e4m3x2.f32 %0, %1, %2;" : "=h"(hi) : "f"(v.w), "f"(v.z));
    uint32_t r;
    asm("mov.b32 %0, {%1, %2};" : "=r"(r) : "h"(lo), "h"(hi));
    return r;
}

// fp8 MMA with f16 accumulators (2-reg D)
__device__ __forceinline__ void mma_fp8_h(uint32_t* d, const uint32_t* a,
                                          uint32_t b0, uint32_t b1) {
    asm volatile(
        "mma.sync.aligned.m16n8k32.row.col.f16.e4m3.e4m3.f16 "
        "{%0,%1}, {%2,%3,%4,%5}, {%6,%7}, {%0,%1};\n"
        : "+r"(d[0]), "+r"(d[1])
        : "r"(a[0]), "r"(a[1]), "r"(a[2]), "r"(a[3]), "r"(b0), "r"(b1));
}

// ------------------------- fused prep kernel --------------------------------
// Blocks 0-63: Wa -> e4m3 B-fragment layout (proven R10/R11), pre-scaled x64.
// Blocks 64+: context -> e4m3 A-fragment layout (inverse of the proven R13
//   in-kernel staging map). Per 64-row block: 8 chunks x 1024 u32.
//   out index within chunk: oo = m16*256 + ks*128 + ln*4 + w
//   inverse: f = (ln&3)|((w&2)<<1)|(ks<<3), r = m16*16+((w&1)<<3)+(ln>>2)
__global__ void quant_prep_kernel(const float* __restrict__ Wa,
                                  const float* __restrict__ ctx,
                                  uint32_t* __restrict__ waq,
                                  uint32_t* __restrict__ ctx8) {
    __shared__ float s[64][65];
    int tid = threadIdx.x;              // 256
    if (blockIdx.x < 64) {
        int kt = blockIdx.x >> 3;
        int nbg = blockIdx.x & 7;
        int k0 = kt * 64, n0 = nbg * 64;
#pragma unroll
        for (int i = 0; i < 16; i++) {
            int idx = tid + i * 256;
            int kl = idx >> 6, nl = idx & 63;
            s[kl][nl] = Wa[(k0 + kl) * UNITS + n0 + nl];
        }
        __syncthreads();
#pragma unroll
        for (int j = 0; j < 4; j++) {
            int wi = tid + j * 256;
            int nb_l = wi >> 7;
            int rem = wi & 127;
            int lane = rem >> 2, w = rem & 3;
            int n_l = nb_l * 8 + (lane >> 2);
            int kb = ((w & 1) ? 16 : 0) + ((w & 2) ? 32 : 0) + (lane & 3) * 4;
            float4 v = make_float4(s[kb][n_l] * BSCALE, s[kb + 1][n_l] * BSCALE,
                                   s[kb + 2][n_l] * BSCALE, s[kb + 3][n_l] * BSCALE);
            waq[((kt * 64 + nbg * 8 + nb_l) * 32 + lane) * 4 + w] = pack_e4m3(v);
        }
    } else {
        // context converter: one uint4 (4 consecutive u32 outputs, w=0..3)
        size_t gid = (size_t)(blockIdx.x - 64) * 256 + tid;    // 0..4194303
        size_t o = gid * 4;
        int blk = (int)(o >> 13);          // 64-row block (2048 of them)
        int rem = (int)(o & 8191);
        int kt = rem >> 10;
        int oo = rem & 1023;               // w = 0 here
        int ln = (oo >> 2) & 31, ks = (oo >> 7) & 1, m16 = oo >> 8;
        int f0 = (ln & 3) | (ks << 3);
        int r0 = m16 * 16 + (ln >> 2);
        const float4* src = (const float4*)ctx + (size_t)blk * 8192 + kt * 16;
        uint32_t q0 = pack_e4m3(src[(size_t)r0 * 128 + f0]);          // w=0
        uint32_t q1 = pack_e4m3(src[(size_t)(r0 + 8) * 128 + f0]);    // w=1
        uint32_t q2 = pack_e4m3(src[(size_t)r0 * 128 + f0 + 4]);      // w=2
        uint32_t q3 = pack_e4m3(src[(size_t)(r0 + 8) * 128 + f0 + 4]);// w=3
        ((uint4*)ctx8)[gid] = make_uint4(q0, q1, q2, q3);
    }
}

// ------------------------- shared 64x64 GEMM body ---------------------------
__device__ __forceinline__ void gemm64_body(
    float (*As_t)[68], float (*Bs)[68],
    const float* __restrict__ A, int lda,
    const float* __restrict__ B, int ldb, int bcol0,
    int k0, int Kc, float* __restrict__ P, int N, int outn, int prow0) {
    int tid = threadIdx.x;
    int tx = tid & 15, ty = tid >> 4;
    float acc[4][4];
#pragma unroll
    for (int i = 0; i < 4; i++)
#pragma unroll
        for (int j = 0; j < 4; j++) acc[i][j] = 0.f;

    int am = tid >> 2, aj = tid & 3;
    int bk = tid >> 4, bf = tid & 15;

    for (int kb = 0; kb < Kc; kb += 16) {
        float4 av = *(const float4*)&A[am * lda + k0 + kb + aj * 4];
        float4 bv = *(const float4*)&B[(size_t)(k0 + kb + bk) * ldb + bcol0 + bf * 4];
        As_t[aj * 4 + 0][am] = av.x;
        As_t[aj * 4 + 1][am] = av.y;
        As_t[aj * 4 + 2][am] = av.z;
        As_t[aj * 4 + 3][am] = av.w;
        *(float4*)&Bs[bk][bf * 4] = bv;
        __syncthreads();
#pragma unroll
        for (int k = 0; k < 16; k++) {
            float4 a = *(const float4*)&As_t[k][ty * 4];
            float4 b = *(const float4*)&Bs[k][tx * 4];
            acc[0][0] = fmaf(a.x, b.x, acc[0][0]);
            acc[0][1] = fmaf(a.x, b.y, acc[0][1]);
            acc[0][2] = fmaf(a.x, b.z, acc[0][2]);
            acc[0][3] = fmaf(a.x, b.w, acc[0][3]);
            acc[1][0] = fmaf(a.y, b.x, acc[1][0]);
            acc[1][1] = fmaf(a.y, b.y, acc[1][1]);
            acc[1][2] = fmaf(a.y, b.z, acc[1][2]);
            acc[1][3] = fmaf(a.y, b.w, acc[1][3]);
            acc[2][0] = fmaf(a.z, b.x, acc[2][0]);
            acc[2][1] = fmaf(a.z, b.y, acc[2][1]);
            acc[2][2] = fmaf(a.z, b.z, acc[2][2]);
            acc[2][3] = fmaf(a.z, b.w, acc[2][3]);
            acc[3][0] = fmaf(a.w, b.x, acc[3][0]);
            acc[3][1] = fmaf(a.w, b.y, acc[3][1]);
            acc[3][2] = fmaf(a.w, b.z, acc[3][2]);
            acc[3][3] = fmaf(a.w, b.w, acc[3][3]);
        }
        __syncthreads();
    }
#pragma unroll
    for (int i = 0; i < 4; i++) {
        float4 r = make_float4(acc[i][0], acc[i][1], acc[i][2], acc[i][3]);
        *(float4*)&P[(size_t)(prow0 + ty * 4 + i) * N + outn + tx * 4] = r;
    }
}

__global__ __launch_bounds__(256)
void gemm64_kernel(const float* __restrict__ A, int lda,
                   const float* __restrict__ B, int ldb, int bcol0,
                   float* __restrict__ P, int N) {
    __shared__ float As_t[16][68];
    __shared__ float Bs[16][68];
    int n0 = blockIdx.x * 64;
    int ks = blockIdx.y;
    gemm64_body(As_t, Bs, A, lda, B, ldb, bcol0 + n0, ks * 64, 64, P, N, n0, ks * 64);
}

// merged pre-score GEMMs: x (32 CTAs), qplus (64), reczr (128) -> 224 CTAs
__global__ __launch_bounds__(256)
void gemm64_multi_kernel(const float* __restrict__ inputs,
                         const float* __restrict__ h_tm1,
                         const float* __restrict__ Wi,
                         const float* __restrict__ Ua,
                         const float* __restrict__ reck,
                         float* __restrict__ gp) {
    __shared__ float As_t[16][68];
    __shared__ float Bs[16][68];
    int bid = blockIdx.x;
    if (bid < 32) {
        int nb = bid & 7, ks = bid >> 3;
        gemm64_body(As_t, Bs, inputs, EMB, Wi, 512, nb * 64, ks * 64, 64,
                    gp + GP_X, 512, nb * 64, ks * 64);
    } else if (bid < 96) {
        int idx = bid - 32;
        int nb = idx & 7, ks = idx >> 3;
        gemm64_body(As_t, Bs, h_tm1, 512, Ua, 512, nb * 64, ks * 64, 64,
                    gp + GP_Q, 512, nb * 64, ks * 64);
    } else {
        int idx = bid - 96;
        int nb = idx & 15, ks = idx >> 4;
        gemm64_body(As_t, Bs, h_tm1, 512, reck, 1536, nb * 64, ks * 64, 64,
                    gp + GP_R, 1024, nb * 64, ks * 64);
    }
}

__global__ void reduce_multi_kernel(const float* __restrict__ gp,
                                    const float* __restrict__ bi,
                                    const float* __restrict__ ba_u,
                                    const float* __restrict__ ba_w,
                                    float* __restrict__ x,
                                    float* __restrict__ qplus,
                                    float* __restrict__ reczr) {
    int idx = blockIdx.x * 256 + threadIdx.x;
    if (idx < 32768) {
        int m = idx >> 9, n = idx & 511;
        float s = 0.f;
#pragma unroll
        for (int ks = 0; ks < 4; ks++) s += gp[GP_X + (size_t)(ks * 64 + m) * 512 + n];
        x[m * 512 + n] = s + bi[n];
    } else if (idx < 65536) {
        int i = idx - 32768;
        int m = i >> 9, n = i & 511;
        float s = 0.f;
#pragma unroll
        for (int ks = 0; ks < 8; ks++) s += gp[GP_Q + (size_t)(ks * 64 + m) * 512 + n];
        qplus[m * 512 + n] = s + ba_u[n] + ba_w[n];
    } else {
        int i = idx - 65536;
        int m = i >> 10, n = i & 1023;
        float s = 0.f;
#pragma unroll
        for (int ks = 0; ks < 8; ks++) s += gp[GP_R + (size_t)(ks * 64 + m) * 1024 + n];
        reczr[m * 1024 + n] = s;
    }
}

__global__ void reduce64_kernel(const float* __restrict__ P, int N, int KS,
                                const float* __restrict__ b1,
                                float* __restrict__ C, int ldc) {
    int m = blockIdx.y;
    int n = blockIdx.x * 256 + threadIdx.x;
    float s = 0.f;
    for (int ks = 0; ks < KS; ks++) s += P[(size_t)(ks * 64 + m) * N + n];
    if (b1) s += b1[n];
    C[m * ldc + n] = s;
}

// ------------------------- fp8 fused score GEMM (f16 accum, BN=512) ---------
// BM=64, BN=512, K=512 in 8 chunks. 256 threads, grid 2048, 1 CTA/SM.
// BOTH operands pre-packed in global fragment order -> staging is pure
// cp.async (1 A + 8 B per thread per chunk). No converts/LDG deps in loop.
__global__ __launch_bounds__(256, 1)
void score_fp8_kernel(const uint32_t* __restrict__ ctx8,
                      const uint32_t* __restrict__ WaQ,
                      const float* __restrict__ qplus,
                      const float* __restrict__ Va,
                      float* __restrict__ score) {
    extern __shared__ uint32_t smem[];
    uint32_t* Abuf[2] = {smem, smem + 1024};            // 4KB each
    uint32_t* Bbuf[2] = {smem + 2048, smem + 10240};    // 32KB each

    const int tid = threadIdx.x;
    const int wid = tid >> 5;
    const int lane = tid & 31;
    const int wm = wid >> 2;            // 0..1: 32-row slice
    const int wn = wid & 3;             // 0..3: 128-col slice
    const size_t row0 = (size_t)blockIdx.x * 64;
    const int b = blockIdx.x >> 5;      // 32 CTAs per batch

    const uint32_t* asrc = ctx8 + (size_t)blockIdx.x * 8192;

    uint32_t acc[2][16][2];
#pragma unroll
    for (int i = 0; i < 2; i++)
#pragma unroll
        for (int j = 0; j < 16; j++) { acc[i][j][0] = 0u; acc[i][j][1] = 0u; }

    // ---- prologue: stage chunk 0 ----
    cp16((char*)Abuf[0] + tid * 16, asrc + (size_t)tid * 4);
#pragma unroll
    for (int i = 0; i < 8; i++) {
        int idx = tid + i * 256;
        cp16((char*)Bbuf[0] + idx * 16, WaQ + (size_t)idx * 4);
    }
    CP_COMMIT();
    CP_WAIT0();
    __syncthreads();

    // ---- main loop over 8 K-chunks ----
    for (int kt = 0; kt < 8; kt++) {
        const int cur = kt & 1, nxt = cur ^ 1;
        if (kt < 7) {
            cp16((char*)Abuf[nxt] + tid * 16,
                 asrc + (size_t)(kt + 1) * 1024 + (size_t)tid * 4);
            const uint32_t* bs = WaQ + (size_t)(kt + 1) * 8192;
#pragma unroll
            for (int i = 0; i < 8; i++) {
                int idx = tid + i * 256;
                cp16((char*)Bbuf[nxt] + idx * 16, bs + (size_t)idx * 4);
            }
            CP_COMMIT();
        }

        const uint32_t* As = Abuf[cur];
        const uint32_t* Bs = Bbuf[cur];
        uint32_t a[2][2][4];
#pragma unroll
        for (int mt = 0; mt < 2; mt++)
#pragma unroll
            for (int ks = 0; ks < 2; ks++) {
                uint4 av = *(const uint4*)&As[((((wm * 2 + mt) * 2 + ks) * 32) + lane) * 4];
                a[mt][ks][0] = av.x; a[mt][ks][1] = av.y;
                a[mt][ks][2] = av.z; a[mt][ks][3] = av.w;
            }
#pragma unroll
        for (int nt = 0; nt < 16; nt++) {
            uint4 bv = *(const uint4*)&Bs[(((wn * 16 + nt) * 32) + lane) * 4];
#pragma unroll
            for (int mt = 0; mt < 2; mt++) {
                mma_fp8_h(acc[mt][nt], a[mt][0], bv.x, bv.y);
                mma_fp8_h(acc[mt][nt], a[mt][1], bv.z, bv.w);
            }
        }

        if (kt < 7) CP_WAIT0();
        __syncthreads();
    }

    // ---- epilogue: dequant -> +qplus -> tanh -> *Va -> FULL row reduce ----
    float* redf = (float*)smem;          // [64][4]
    float* sq = redf + 256;              // [512]
    float* sv = sq + 512;                // [512]
    for (int i = tid; i < 512; i += 256) {
        sq[i] = qplus[b * UNITS + i];
        sv[i] = Va[i];
    }
    __syncthreads();

    float rsum[2][2] = {{0.f, 0.f}, {0.f, 0.f}};
#pragma unroll
    for (int mt = 0; mt < 2; mt++) {
#pragma unroll
        for (int nt = 0; nt < 16; nt++) {
            int n0 = wn * 128 + nt * 8 + (lane & 3) * 2;
            float q0 = sq[n0], q1 = sq[n0 + 1];
            float v0 = sv[n0], v1 = sv[n0 + 1];
            __half2 h0 = *(__half2*)&acc[mt][nt][0];
            __half2 h1 = *(__half2*)&acc[mt][nt][1];
            rsum[mt][0] += tanh_approx(__low2float(h0) * INV_BS + q0) * v0
                         + tanh_approx(__high2float(h0) * INV_BS + q1) * v1;
            rsum[mt][1] += tanh_approx(__low2float(h1) * INV_BS + q0) * v0
                         + tanh_approx(__high2float(h1) * INV_BS + q1) * v1;
        }
    }
#pragma unroll
    for (int mt = 0; mt < 2; mt++) {
#pragma unroll
        for (int lh = 0; lh < 2; lh++) {
            float s = rsum[mt][lh];
            s += __shfl_xor_sync(0xffffffffu, s, 1);
            s += __shfl_xor_sync(0xffffffffu, s, 2);
            if ((lane & 3) == 0) {
                int r = wm * 32 + mt * 16 + (lane >> 2) + lh * 8;
                redf[r * 4 + wn] = s;
            }
        }
    }
    __syncthreads();
    if (tid < 64) {
        float s = redf[tid * 4] + redf[tid * 4 + 1] +
                  redf[tid * 4 + 2] + redf[tid * 4 + 3];
        score[row0 + tid] = s;
    }
}

// ------------------------- softmax over T per batch -------------------------
__global__ void softmax_kernel(const float* __restrict__ sc,
                               float* __restrict__ attn) {
    int b = blockIdx.x;
    int tid = threadIdx.x;
    __shared__ float red[256];
    float v[8];
    float mx = -1e30f;
#pragma unroll
    for (int i = 0; i < 8; i++) {
        float s = sc[b * TSEQ + i * 256 + tid];
        v[i] = s;
        mx = fmaxf(mx, s);
    }
    red[tid] = mx;
    __syncthreads();
    for (int o = 128; o > 0; o >>= 1) {
        if (tid < o) red[tid] = fmaxf(red[tid], red[tid + o]);
        __syncthreads();
    }
    mx = red[0];
    __syncthreads();
    float sum = 0.f;
#pragma unroll
    for (int i = 0; i < 8; i++) {
        v[i] = expf(v[i] - mx);
        sum += v[i];
    }
    red[tid] = sum;
    __syncthreads();
    for (int o = 128; o > 0; o >>= 1) {
        if (tid < o) red[tid] += red[tid + o];
        __syncthreads();
    }
    float inv = 1.f / red[0];
#pragma unroll
    for (int i = 0; i < 8; i++) attn[b * TSEQ + i * 256 + tid] = v[i] * inv;
}

// ------------------------- ctx_vec = sum_t attn * context -------------------
__global__ void ctx_partial_kernel(const float* __restrict__ context,
                                   const float* __restrict__ attn,
                                   float* __restrict__ partial) {
    int b = blockIdx.x, tc = blockIdx.y;
    int tid = threadIdx.x;
    __shared__ float sa[128];
    sa[tid] = attn[b * TSEQ + tc * 128 + tid];
    __syncthreads();
    const float4* ctx4 =
        (const float4*)context + ((size_t)b * TSEQ + tc * 128) * 128;
    float ax = 0.f, ay = 0.f, az = 0.f, aw = 0.f;
#pragma unroll 8
    for (int t = 0; t < 128; t++) {
        float a = sa[t];
        float4 v = ctx4[(size_t)t * 128 + tid];
        ax = fmaf(a, v.x, ax);
        ay = fmaf(a, v.y, ay);
        az = fmaf(a, v.z, az);
        aw = fmaf(a, v.w, aw);
    }
    float4 r = make_float4(ax, ay, az, aw);
    ((float4*)partial)[(size_t)(b * 16 + tc) * 128 + tid] = r;
}

__global__ void ctx_reduce_kernel(const float* __restrict__ partial,
                                  float* __restrict__ ctxvec) {
    int idx = blockIdx.x * 256 + threadIdx.x;
    int b = idx >> 9, u = idx & 511;
    float s = 0.f;
#pragma unroll
    for (int tc = 0; tc < 16; tc++) s += partial[(size_t)(b * 16 + tc) * UNITS + u];
    ctxvec[idx] = s;
}

// ------------------------- gates (reads cg split-K partials) ----------------
__global__ void gate_kernel(const float* __restrict__ gp,
                            const float* __restrict__ xg,
                            const float* __restrict__ reczr,
                            const float* __restrict__ h_tm1,
                            float* __restrict__ zbuf,
                            float* __restrict__ rh) {
    int idx = blockIdx.x * 256 + threadIdx.x;
    int b = idx >> 9, n = idx & 511;
    float cz = 0.f, cr = 0.f;
#pragma unroll
    for (int ks = 0; ks < 8; ks++) {
        cz += gp[(size_t)(ks * 64 + b) * 1536 + n];
        cr += gp[(size_t)(ks * 64 + b) * 1536 + 512 + n];
    }
    float zin = xg[b * 1536 + n] + reczr[b * 1024 + n] + cz;
    float rin = xg[b * 1536 + 512 + n] + reczr[b * 1024 + 512 + n] + cr;
    float z = 1.f / (1.f + expf(-zin));
    float r = 1.f / (1.f + expf(-rin));
    zbuf[idx] = z;
    rh[idx] = r * h_tm1[idx];
}

// ------------------------- h epilogue (rec_h + cg_h partials) ---------------
__global__ void hfinal_reduce_kernel(const float* __restrict__ gp,
                                     const float* __restrict__ xg,
                                     const float* __restrict__ zbuf,
                                     const float* __restrict__ h_tm1,
                                     float* __restrict__ hbuf,
                                     float* __restrict__ outh) {
    int m = blockIdx.y;
    int n = blockIdx.x * 256 + threadIdx.x;
    float rec_h = 0.f, ch = 0.f;
#pragma unroll
    for (int ks = 0; ks < 8; ks++) {
        rec_h += gp[GP_H + (size_t)(ks * 64 + m) * 512 + n];
        ch    += gp[(size_t)(ks * 64 + m) * 1536 + 1024 + n];
    }
    float hb = tanhf(xg[m * 1536 + 1024 + n] + rec_h + ch);
    float z = zbuf[m * UNITS + n];
    float h = z * h_tm1[m * UNITS + n] + (1.f - z) * hb;
    hbuf[m * UNITS + n] = h;
    outh[m * UNITS + n] = h;
}

// ---------------------------------------------------------------------------
extern "C" void kernel_launch(void* const* d_in, const int* in_sizes, int n_in,
                              void* d_out, int out_size) {
    const float* inputs  = (const float*)d_in[0];
    const float* h_tm1   = (const float*)d_in[1];
    const float* context = (const float*)d_in[2];
    const float* Wi      = (const float*)d_in[3];
    const float* bi      = (const float*)d_in[4];
    const float* kern    = (const float*)d_in[5];
    const float* reck    = (const float*)d_in[6];
    const float* attk    = (const float*)d_in[7];
    const float* bias    = (const float*)d_in[8];
    const float* Wa      = (const float*)d_in[9];
    const float* ba_w    = (const float*)d_in[10];
    const float* Ua      = (const float*)d_in[11];
    const float* ba_u    = (const float*)d_in[12];
    const float* Va      = (const float*)d_in[13];
    /* ba_v (d_in[14]) cancels in softmax */
    const float* Wo      = (const float*)d_in[15];
    const float* bo      = (const float*)d_in[16];

    float* out  = (float*)d_out;
    float* outh = out + BATCH * UNITS;

    float *px, *pxg, *pq, *prec, *psc, *pat, *ppar, *pcv, *pz, *prh, *ph, *pgp;
    uint32_t *pwaq, *pctx8;
    void* tmp;
    cudaGetSymbolAddress(&tmp, g_x);         px   = (float*)tmp;
    cudaGetSymbolAddress(&tmp, g_xg);        pxg  = (float*)tmp;
    cudaGetSymbolAddress(&tmp, g_qplus);     pq   = (float*)tmp;
    cudaGetSymbolAddress(&tmp, g_reczr);     prec = (float*)tmp;
    cudaGetSymbolAddress(&tmp, g_score);     psc  = (float*)tmp;
    cudaGetSymbolAddress(&tmp, g_attn);      pat  = (float*)tmp;
    cudaGetSymbolAddress(&tmp, g_partial);   ppar = (float*)tmp;
    cudaGetSymbolAddress(&tmp, g_ctxvec);    pcv  = (float*)tmp;
    cudaGetSymbolAddress(&tmp, g_z);         pz   = (float*)tmp;
    cudaGetSymbolAddress(&tmp, g_rh);        prh  = (float*)tmp;
    cudaGetSymbolAddress(&tmp, g_h);         ph   = (float*)tmp;
    cudaGetSymbolAddress(&tmp, g_gp);        pgp  = (float*)tmp;
    cudaGetSymbolAddress(&tmp, g_WaQ);       pwaq = (uint32_t*)tmp;
    cudaGetSymbolAddress(&tmp, g_ctx8);      pctx8 = (uint32_t*)tmp;

    // raise dynamic smem limit for the score kernel (72 KB > 48 KB default)
    cudaFuncSetAttribute((const void*)score_fp8_kernel,
                         cudaFuncAttributeMaxDynamicSharedMemorySize, 73728);

    // 1. fused prep: Wa -> B-fragments (64 blocks) + context -> A-fragments
    quant_prep_kernel<<<64 + 16384, 256>>>(Wa, context, pwaq, pctx8);

    // 2. merged: x = inputs@Wi ; qplus = h_tm1@Ua ; reczr = h_tm1@reck[:,:1024]
    gemm64_multi_kernel<<<224, 256>>>(inputs, h_tm1, Wi, Ua, reck, pgp);
    reduce_multi_kernel<<<512, 256>>>(pgp, bi, ba_u, ba_w, px, pq, prec);

    // 3. fp8 fused score GEMM (f16 accum, pure cp.async staging)
    score_fp8_kernel<<<2048, 256, 73728>>>(pctx8, pwaq, pq, Va, psc);

    // 4. xg = x @ kernel + bias   (KS=8)
    gemm64_kernel<<<dim3(24, 8), 256>>>(px, 512, kern, 1536, 0, pgp, 1536);
    reduce64_kernel<<<dim3(6, 64), 256>>>(pgp, 1536, 8, bias, pxg, 1536);

    // 5. softmax over T
    softmax_kernel<<<BATCH, 256>>>(psc, pat);
    // 6. ctx_vec = sum_t attn * context
    ctx_partial_kernel<<<dim3(BATCH, 16), 128>>>(context, pat, ppar);
    ctx_reduce_kernel<<<BATCH * UNITS / 256, 256>>>(ppar, pcv);
    // 7. cg partials = ctx_vec @ attention_kernel (KS=8) -> consumed inline
    gemm64_kernel<<<dim3(24, 8), 256>>>(pcv, 512, attk, 1536, 0, pgp, 1536);
    // 8. z, r gates (sum cg partials inline)
    gate_kernel<<<BATCH * UNITS / 256, 256>>>(pgp, pxg, prec, h_tm1, pz, prh);
    // 9. rec_h partials (disjoint region) + h epilogue (sums rec_h + cg_h)
    gemm64_kernel<<<dim3(8, 8), 256>>>(prh, 512, reck, 1536, 1024, pgp + GP_H, 512);
    hfinal_reduce_kernel<<<dim3(2, 64), 256>>>(pgp, pxg, pz, h_tm1, ph, outh);
    // 10. out = h @ Wo + bo (KS=8)
    gemm64_kernel<<<dim3(8, 8), 256>>>(ph, 512, Wo, 512, 0, pgp, 512);
    reduce64_kernel<<<dim3(2, 64), 256>>>(pgp, 512, 8, bo, out, 512);

    (void)in_sizes; (void)n_in; (void)out_size;
}

// round 17
// speedup vs baseline: 1.2128x; 1.1588x over previous
#include <cuda_runtime.h>
#include <cuda_bf16.h>
#include <cuda_fp16.h>
#include <math.h>
#include <stdint.h>

#define BATCH 64
#define TSEQ  2048
#define UNITS 512
#define EMB   256
#define ROWS  (BATCH * TSEQ)   // 131072

#define BSCALE 64.0f           // Wa pre-scale into e4m3 range
#define INV_BS (1.0f / 64.0f)

// ------------------------- device scratch ----------------------------------
__device__ float g_x[BATCH * UNITS];
__device__ float g_xg[BATCH * 3 * UNITS];
__device__ float g_qplus[BATCH * UNITS];
__device__ float g_reczr[BATCH * 2 * UNITS];
__device__ float g_score[ROWS];
__device__ float g_attn[BATCH * TSEQ];
__device__ float g_partial[BATCH * 16 * UNITS];
__device__ float g_ctxvec[BATCH * UNITS];
__device__ float g_z[BATCH * UNITS];
__device__ float g_rh[BATCH * UNITS];
__device__ float g_h[BATCH * UNITS];
__device__ float g_gp[1048576];            // split-K partials (4MB)
__device__ uint32_t g_WaQ[65536];          // Wa e4m3, B-fragment order
__device__ uint32_t g_ctx8[16777216];      // context e4m3, A-fragment order (64MB)

// partial regions inside g_gp for the merged pre-score GEMMs
#define GP_X  0          // [4][64][512]
#define GP_Q  131072     // [8][64][512]
#define GP_R  393216     // [8][64][1024]
#define GP_H  786432     // [8][64][512]  rec_h partials (disjoint from cg base)

// ------------------------- helpers -----------------------------------------
__device__ __forceinline__ void cp16(void* dst_smem, const void* src) {
    uint32_t d = (uint32_t)__cvta_generic_to_shared(dst_smem);
    asm volatile("cp.async.cg.shared.global [%0], [%1], 16;\n" :: "r"(d), "l"(src));
}
#define CP_COMMIT() asm volatile("cp.async.commit_group;\n" ::)
#define CP_WAIT0()  asm volatile("cp.async.wait_group 0;\n" ::)

__device__ __forceinline__ float tanh_approx(float x) {
    float y;
    asm("tanh.approx.f32 %0, %1;" : "=f"(y) : "f"(x));
    return y;
}

// pack 4 floats (k-ascending) into 4 e4m3 bytes
__device__ __forceinline__ uint32_t pack_e4m3(float4 v) {
    uint16_t lo, hi;
    asm("cvt.rn.satfinite.e4m3x2.f32 %0, %1, %2;" : "=h"(lo) : "f"(v.y), "f"(v.x));
    asm("cvt.rn.satfinite.e4m3x2.f32 %0, %1, %2;" : "=h"(hi) : "f"(v.w), "f"(v.z));
    uint32_t r;
    asm("mov.b32 %0, {%1, %2};" : "=r"(r) : "h"(lo), "h"(hi));
    return r;
}

// fp8 MMA with f16 accumulators (2-reg D)
__device__ __forceinline__ void mma_fp8_h(uint32_t* d, const uint32_t* a,
                                          uint32_t b0, uint32_t b1) {
    asm volatile(
        "mma.sync.aligned.m16n8k32.row.col.f16.e4m3.e4m3.f16 "
        "{%0,%1}, {%2,%3,%4,%5}, {%6,%7}, {%0,%1};\n"
        : "+r"(d[0]), "+r"(d[1])
        : "r"(a[0]), "r"(a[1]), "r"(a[2]), "r"(a[3]), "r"(b0), "r"(b1));
}

// ------------------------- fused prep kernel --------------------------------
// Blocks 0-63: Wa -> e4m3 B-fragment layout (proven R10/R11), pre-scaled x64.
// Blocks 64+: context -> e4m3 A-fragment layout (proven R16).
__global__ void quant_prep_kernel(const float* __restrict__ Wa,
                                  const float* __restrict__ ctx,
                                  uint32_t* __restrict__ waq,
                                  uint32_t* __restrict__ ctx8) {
    __shared__ float s[64][65];
    int tid = threadIdx.x;              // 256
    if (blockIdx.x < 64) {
        int kt = blockIdx.x >> 3;
        int nbg = blockIdx.x & 7;
        int k0 = kt * 64, n0 = nbg * 64;
#pragma unroll
        for (int i = 0; i < 16; i++) {
            int idx = tid + i * 256;
            int kl = idx >> 6, nl = idx & 63;
            s[kl][nl] = Wa[(k0 + kl) * UNITS + n0 + nl];
        }
        __syncthreads();
#pragma unroll
        for (int j = 0; j < 4; j++) {
            int wi = tid + j * 256;
            int nb_l = wi >> 7;
            int rem = wi & 127;
            int lane = rem >> 2, w = rem & 3;
            int n_l = nb_l * 8 + (lane >> 2);
            int kb = ((w & 1) ? 16 : 0) + ((w & 2) ? 32 : 0) + (lane & 3) * 4;
            float4 v = make_float4(s[kb][n_l] * BSCALE, s[kb + 1][n_l] * BSCALE,
                                   s[kb + 2][n_l] * BSCALE, s[kb + 3][n_l] * BSCALE);
            waq[((kt * 64 + nbg * 8 + nb_l) * 32 + lane) * 4 + w] = pack_e4m3(v);
        }
    } else {
        size_t gid = (size_t)(blockIdx.x - 64) * 256 + tid;    // 0..4194303
        size_t o = gid * 4;
        int blk = (int)(o >> 13);
        int rem = (int)(o & 8191);
        int kt = rem >> 10;
        int oo = rem & 1023;
        int ln = (oo >> 2) & 31, ks = (oo >> 7) & 1, m16 = oo >> 8;
        int f0 = (ln & 3) | (ks << 3);
        int r0 = m16 * 16 + (ln >> 2);
        const float4* src = (const float4*)ctx + (size_t)blk * 8192 + kt * 16;
        uint32_t q0 = pack_e4m3(src[(size_t)r0 * 128 + f0]);
        uint32_t q1 = pack_e4m3(src[(size_t)(r0 + 8) * 128 + f0]);
        uint32_t q2 = pack_e4m3(src[(size_t)r0 * 128 + f0 + 4]);
        uint32_t q3 = pack_e4m3(src[(size_t)(r0 + 8) * 128 + f0 + 4]);
        ((uint4*)ctx8)[gid] = make_uint4(q0, q1, q2, q3);
    }
}

// ------------------------- shared 64x64 GEMM body ---------------------------
__device__ __forceinline__ void gemm64_body(
    float (*As_t)[68], float (*Bs)[68],
    const float* __restrict__ A, int lda,
    const float* __restrict__ B, int ldb, int bcol0,
    int k0, int Kc, float* __restrict__ P, int N, int outn, int prow0) {
    int tid = threadIdx.x;
    int tx = tid & 15, ty = tid >> 4;
    float acc[4][4];
#pragma unroll
    for (int i = 0; i < 4; i++)
#pragma unroll
        for (int j = 0; j < 4; j++) acc[i][j] = 0.f;

    int am = tid >> 2, aj = tid & 3;
    int bk = tid >> 4, bf = tid & 15;

    for (int kb = 0; kb < Kc; kb += 16) {
        float4 av = *(const float4*)&A[am * lda + k0 + kb + aj * 4];
        float4 bv = *(const float4*)&B[(size_t)(k0 + kb + bk) * ldb + bcol0 + bf * 4];
        As_t[aj * 4 + 0][am] = av.x;
        As_t[aj * 4 + 1][am] = av.y;
        As_t[aj * 4 + 2][am] = av.z;
        As_t[aj * 4 + 3][am] = av.w;
        *(float4*)&Bs[bk][bf * 4] = bv;
        __syncthreads();
#pragma unroll
        for (int k = 0; k < 16; k++) {
            float4 a = *(const float4*)&As_t[k][ty * 4];
            float4 b = *(const float4*)&Bs[k][tx * 4];
            acc[0][0] = fmaf(a.x, b.x, acc[0][0]);
            acc[0][1] = fmaf(a.x, b.y, acc[0][1]);
            acc[0][2] = fmaf(a.x, b.z, acc[0][2]);
            acc[0][3] = fmaf(a.x, b.w, acc[0][3]);
            acc[1][0] = fmaf(a.y, b.x, acc[1][0]);
            acc[1][1] = fmaf(a.y, b.y, acc[1][1]);
            acc[1][2] = fmaf(a.y, b.z, acc[1][2]);
            acc[1][3] = fmaf(a.y, b.w, acc[1][3]);
            acc[2][0] = fmaf(a.z, b.x, acc[2][0]);
            acc[2][1] = fmaf(a.z, b.y, acc[2][1]);
            acc[2][2] = fmaf(a.z, b.z, acc[2][2]);
            acc[2][3] = fmaf(a.z, b.w, acc[2][3]);
            acc[3][0] = fmaf(a.w, b.x, acc[3][0]);
            acc[3][1] = fmaf(a.w, b.y, acc[3][1]);
            acc[3][2] = fmaf(a.w, b.z, acc[3][2]);
            acc[3][3] = fmaf(a.w, b.w, acc[3][3]);
        }
        __syncthreads();
    }
#pragma unroll
    for (int i = 0; i < 4; i++) {
        float4 r = make_float4(acc[i][0], acc[i][1], acc[i][2], acc[i][3]);
        *(float4*)&P[(size_t)(prow0 + ty * 4 + i) * N + outn + tx * 4] = r;
    }
}

__global__ __launch_bounds__(256)
void gemm64_kernel(const float* __restrict__ A, int lda,
                   const float* __restrict__ B, int ldb, int bcol0,
                   float* __restrict__ P, int N) {
    __shared__ float As_t[16][68];
    __shared__ float Bs[16][68];
    int n0 = blockIdx.x * 64;
    int ks = blockIdx.y;
    gemm64_body(As_t, Bs, A, lda, B, ldb, bcol0 + n0, ks * 64, 64, P, N, n0, ks * 64);
}

// merged pre-score GEMMs: x (32 CTAs), qplus (64), reczr (128) -> 224 CTAs
__global__ __launch_bounds__(256)
void gemm64_multi_kernel(const float* __restrict__ inputs,
                         const float* __restrict__ h_tm1,
                         const float* __restrict__ Wi,
                         const float* __restrict__ Ua,
                         const float* __restrict__ reck,
                         float* __restrict__ gp) {
    __shared__ float As_t[16][68];
    __shared__ float Bs[16][68];
    int bid = blockIdx.x;
    if (bid < 32) {
        int nb = bid & 7, ks = bid >> 3;
        gemm64_body(As_t, Bs, inputs, EMB, Wi, 512, nb * 64, ks * 64, 64,
                    gp + GP_X, 512, nb * 64, ks * 64);
    } else if (bid < 96) {
        int idx = bid - 32;
        int nb = idx & 7, ks = idx >> 3;
        gemm64_body(As_t, Bs, h_tm1, 512, Ua, 512, nb * 64, ks * 64, 64,
                    gp + GP_Q, 512, nb * 64, ks * 64);
    } else {
        int idx = bid - 96;
        int nb = idx & 15, ks = idx >> 4;
        gemm64_body(As_t, Bs, h_tm1, 512, reck, 1536, nb * 64, ks * 64, 64,
                    gp + GP_R, 1024, nb * 64, ks * 64);
    }
}

__global__ void reduce_multi_kernel(const float* __restrict__ gp,
                                    const float* __restrict__ bi,
                                    const float* __restrict__ ba_u,
                                    const float* __restrict__ ba_w,
                                    float* __restrict__ x,
                                    float* __restrict__ qplus,
                                    float* __restrict__ reczr) {
    int idx = blockIdx.x * 256 + threadIdx.x;
    if (idx < 32768) {
        int m = idx >> 9, n = idx & 511;
        float s = 0.f;
#pragma unroll
        for (int ks = 0; ks < 4; ks++) s += gp[GP_X + (size_t)(ks * 64 + m) * 512 + n];
        x[m * 512 + n] = s + bi[n];
    } else if (idx < 65536) {
        int i = idx - 32768;
        int m = i >> 9, n = i & 511;
        float s = 0.f;
#pragma unroll
        for (int ks = 0; ks < 8; ks++) s += gp[GP_Q + (size_t)(ks * 64 + m) * 512 + n];
        qplus[m * 512 + n] = s + ba_u[n] + ba_w[n];
    } else {
        int i = idx - 65536;
        int m = i >> 10, n = i & 1023;
        float s = 0.f;
#pragma unroll
        for (int ks = 0; ks < 8; ks++) s += gp[GP_R + (size_t)(ks * 64 + m) * 1024 + n];
        reczr[m * 1024 + n] = s;
    }
}

__global__ void reduce64_kernel(const float* __restrict__ P, int N, int KS,
                                const float* __restrict__ b1,
                                float* __restrict__ C, int ldc) {
    int m = blockIdx.y;
    int n = blockIdx.x * 256 + threadIdx.x;
    float s = 0.f;
    for (int ks = 0; ks < KS; ks++) s += P[(size_t)(ks * 64 + m) * N + n];
    if (b1) s += b1[n];
    C[m * ldc + n] = s;
}

// ------------------------- fp8 fused score GEMM (512 threads) ---------------
// BM=64, BN=512, K=512 in 8 chunks. 512 threads = 16 warps (4/SMSP) so the
// ~33-cyc dependent-MMA latency is covered by warp parallelism (R16: 8 warps
// -> tensor capped at 45%). Warp tile 32x64: wm=wid>>3, wn=wid&7.
// acc = 32 regs/thread; live set ~80 regs -> full 16-warp residency.
__global__ __launch_bounds__(512, 1)
void score_fp8_kernel(const uint32_t* __restrict__ ctx8,
                      const uint32_t* __restrict__ WaQ,
                      const float* __restrict__ qplus,
                      const float* __restrict__ Va,
                      float* __restrict__ score) {
    extern __shared__ uint32_t smem[];
    uint32_t* Abuf[2] = {smem, smem + 1024};            // 4KB each
    uint32_t* Bbuf[2] = {smem + 2048, smem + 10240};    // 32KB each

    const int tid = threadIdx.x;
    const int wid = tid >> 5;
    const int lane = tid & 31;
    const int wm = wid >> 3;            // 0..1: 32-row slice
    const int wn = wid & 7;             // 0..7: 64-col slice
    const size_t row0 = (size_t)blockIdx.x * 64;
    const int b = blockIdx.x >> 5;      // 32 CTAs per batch

    const uint32_t* asrc = ctx8 + (size_t)blockIdx.x * 8192;

    uint32_t acc[2][8][2];
#pragma unroll
    for (int i = 0; i < 2; i++)
#pragma unroll
        for (int j = 0; j < 8; j++) { acc[i][j][0] = 0u; acc[i][j][1] = 0u; }

    // ---- prologue: stage chunk 0 ----
    if (tid < 256) cp16((char*)Abuf[0] + tid * 16, asrc + (size_t)tid * 4);
#pragma unroll
    for (int i = 0; i < 4; i++) {
        int idx = tid + i * 512;
        cp16((char*)Bbuf[0] + idx * 16, WaQ + (size_t)idx * 4);
    }
    CP_COMMIT();
    CP_WAIT0();
    __syncthreads();

    // ---- main loop over 8 K-chunks ----
    for (int kt = 0; kt < 8; kt++) {
        const int cur = kt & 1, nxt = cur ^ 1;
        if (kt < 7) {
            if (tid < 256)
                cp16((char*)Abuf[nxt] + tid * 16,
                     asrc + (size_t)(kt + 1) * 1024 + (size_t)tid * 4);
            const uint32_t* bs = WaQ + (size_t)(kt + 1) * 8192;
#pragma unroll
            for (int i = 0; i < 4; i++) {
                int idx = tid + i * 512;
                cp16((char*)Bbuf[nxt] + idx * 16, bs + (size_t)idx * 4);
            }
            CP_COMMIT();
        }

        const uint32_t* As = Abuf[cur];
        const uint32_t* Bs = Bbuf[cur];
        uint32_t a[2][2][4];
#pragma unroll
        for (int mt = 0; mt < 2; mt++)
#pragma unroll
            for (int ks = 0; ks < 2; ks++) {
                uint4 av = *(const uint4*)&As[((((wm * 2 + mt) * 2 + ks) * 32) + lane) * 4];
                a[mt][ks][0] = av.x; a[mt][ks][1] = av.y;
                a[mt][ks][2] = av.z; a[mt][ks][3] = av.w;
            }
#pragma unroll
        for (int nt = 0; nt < 8; nt++) {
            uint4 bv = *(const uint4*)&Bs[(((wn * 8 + nt) * 32) + lane) * 4];
#pragma unroll
            for (int mt = 0; mt < 2; mt++) {
                mma_fp8_h(acc[mt][nt], a[mt][0], bv.x, bv.y);
                mma_fp8_h(acc[mt][nt], a[mt][1], bv.z, bv.w);
            }
        }

        if (kt < 7) CP_WAIT0();
        __syncthreads();
    }

    // ---- epilogue: dequant -> +qplus -> tanh -> *Va -> FULL row reduce ----
    float* redf = (float*)smem;          // [64][8]
    float* sq = redf + 512;              // [512]
    float* sv = sq + 512;                // [512]
    if (tid < 512) {
        sq[tid] = qplus[b * UNITS + tid];
        sv[tid] = Va[tid];
    }
    __syncthreads();

    float rsum[2][2] = {{0.f, 0.f}, {0.f, 0.f}};
#pragma unroll
    for (int mt = 0; mt < 2; mt++) {
#pragma unroll
        for (int nt = 0; nt < 8; nt++) {
            int n0 = wn * 64 + nt * 8 + (lane & 3) * 2;
            float q0 = sq[n0], q1 = sq[n0 + 1];
            float v0 = sv[n0], v1 = sv[n0 + 1];
            __half2 h0 = *(__half2*)&acc[mt][nt][0];
            __half2 h1 = *(__half2*)&acc[mt][nt][1];
            rsum[mt][0] += tanh_approx(__low2float(h0) * INV_BS + q0) * v0
                         + tanh_approx(__high2float(h0) * INV_BS + q1) * v1;
            rsum[mt][1] += tanh_approx(__low2float(h1) * INV_BS + q0) * v0
                         + tanh_approx(__high2float(h1) * INV_BS + q1) * v1;
        }
    }
#pragma unroll
    for (int mt = 0; mt < 2; mt++) {
#pragma unroll
        for (int lh = 0; lh < 2; lh++) {
            float s = rsum[mt][lh];
            s += __shfl_xor_sync(0xffffffffu, s, 1);
            s += __shfl_xor_sync(0xffffffffu, s, 2);
            if ((lane & 3) == 0) {
                int r = wm * 32 + mt * 16 + (lane >> 2) + lh * 8;
                redf[r * 8 + wn] = s;
            }
        }
    }
    __syncthreads();
    if (tid < 64) {
        float s = 0.f;
#pragma unroll
        for (int j = 0; j < 8; j++) s += redf[tid * 8 + j];
        score[row0 + tid] = s;
    }
}

// ------------------------- softmax over T per batch -------------------------
__global__ void softmax_kernel(const float* __restrict__ sc,
                               float* __restrict__ attn) {
    int b = blockIdx.x;
    int tid = threadIdx.x;
    __shared__ float red[256];
    float v[8];
    float mx = -1e30f;
#pragma unroll
    for (int i = 0; i < 8; i++) {
        float s = sc[b * TSEQ + i * 256 + tid];
        v[i] = s;
        mx = fmaxf(mx, s);
    }
    red[tid] = mx;
    __syncthreads();
    for (int o = 128; o > 0; o >>= 1) {
        if (tid < o) red[tid] = fmaxf(red[tid], red[tid + o]);
        __syncthreads();
    }
    mx = red[0];
    __syncthreads();
    float sum = 0.f;
#pragma unroll
    for (int i = 0; i < 8; i++) {
        v[i] = expf(v[i] - mx);
        sum += v[i];
    }
    red[tid] = sum;
    __syncthreads();
    for (int o = 128; o > 0; o >>= 1) {
        if (tid < o) red[tid] += red[tid + o];
        __syncthreads();
    }
    float inv = 1.f / red[0];
#pragma unroll
    for (int i = 0; i < 8; i++) attn[b * TSEQ + i * 256 + tid] = v[i] * inv;
}

// ------------------------- ctx_vec = sum_t attn * context -------------------
__global__ void ctx_partial_kernel(const float* __restrict__ context,
                                   const float* __restrict__ attn,
                                   float* __restrict__ partial) {
    int b = blockIdx.x, tc = blockIdx.y;
    int tid = threadIdx.x;
    __shared__ float sa[128];
    sa[tid] = attn[b * TSEQ + tc * 128 + tid];
    __syncthreads();
    const float4* ctx4 =
        (const float4*)context + ((size_t)b * TSEQ + tc * 128) * 128;
    float ax = 0.f, ay = 0.f, az = 0.f, aw = 0.f;
#pragma unroll 8
    for (int t = 0; t < 128; t++) {
        float a = sa[t];
        float4 v = ctx4[(size_t)t * 128 + tid];
        ax = fmaf(a, v.x, ax);
        ay = fmaf(a, v.y, ay);
        az = fmaf(a, v.z, az);
        aw = fmaf(a, v.w, aw);
    }
    float4 r = make_float4(ax, ay, az, aw);
    ((float4*)partial)[(size_t)(b * 16 + tc) * 128 + tid] = r;
}

__global__ void ctx_reduce_kernel(const float* __restrict__ partial,
                                  float* __restrict__ ctxvec) {
    int idx = blockIdx.x * 256 + threadIdx.x;
    int b = idx >> 9, u = idx & 511;
    float s = 0.f;
#pragma unroll
    for (int tc = 0; tc < 16; tc++) s += partial[(size_t)(b * 16 + tc) * UNITS + u];
    ctxvec[idx] = s;
}

// ------------------------- gates (reads cg split-K partials) ----------------
__global__ void gate_kernel(const float* __restrict__ gp,
                            const float* __restrict__ xg,
                            const float* __restrict__ reczr,
                            const float* __restrict__ h_tm1,
                            float* __restrict__ zbuf,
                            float* __restrict__ rh) {
    int idx = blockIdx.x * 256 + threadIdx.x;
    int b = idx >> 9, n = idx & 511;
    float cz = 0.f, cr = 0.f;
#pragma unroll
    for (int ks = 0; ks < 8; ks++) {
        cz += gp[(size_t)(ks * 64 + b) * 1536 + n];
        cr += gp[(size_t)(ks * 64 + b) * 1536 + 512 + n];
    }
    float zin = xg[b * 1536 + n] + reczr[b * 1024 + n] + cz;
    float rin = xg[b * 1536 + 512 + n] + reczr[b * 1024 + 512 + n] + cr;
    float z = 1.f / (1.f + expf(-zin));
    float r = 1.f / (1.f + expf(-rin));
    zbuf[idx] = z;
    rh[idx] = r * h_tm1[idx];
}

// ------------------------- h epilogue (rec_h + cg_h partials) ---------------
__global__ void hfinal_reduce_kernel(const float* __restrict__ gp,
                                     const float* __restrict__ xg,
                                     const float* __restrict__ zbuf,
                                     const float* __restrict__ h_tm1,
                                     float* __restrict__ hbuf,
                                     float* __restrict__ outh) {
    int m = blockIdx.y;
    int n = blockIdx.x * 256 + threadIdx.x;
    float rec_h = 0.f, ch = 0.f;
#pragma unroll
    for (int ks = 0; ks < 8; ks++) {
        rec_h += gp[GP_H + (size_t)(ks * 64 + m) * 512 + n];
        ch    += gp[(size_t)(ks * 64 + m) * 1536 + 1024 + n];
    }
    float hb = tanhf(xg[m * 1536 + 1024 + n] + rec_h + ch);
    float z = zbuf[m * UNITS + n];
    float h = z * h_tm1[m * UNITS + n] + (1.f - z) * hb;
    hbuf[m * UNITS + n] = h;
    outh[m * UNITS + n] = h;
}

// ---------------------------------------------------------------------------
extern "C" void kernel_launch(void* const* d_in, const int* in_sizes, int n_in,
                              void* d_out, int out_size) {
    const float* inputs  = (const float*)d_in[0];
    const float* h_tm1   = (const float*)d_in[1];
    const float* context = (const float*)d_in[2];
    const float* Wi      = (const float*)d_in[3];
    const float* bi      = (const float*)d_in[4];
    const float* kern    = (const float*)d_in[5];
    const float* reck    = (const float*)d_in[6];
    const float* attk    = (const float*)d_in[7];
    const float* bias    = (const float*)d_in[8];
    const float* Wa      = (const float*)d_in[9];
    const float* ba_w    = (const float*)d_in[10];
    const float* Ua      = (const float*)d_in[11];
    const float* ba_u    = (const float*)d_in[12];
    const float* Va      = (const float*)d_in[13];
    /* ba_v (d_in[14]) cancels in softmax */
    const float* Wo      = (const float*)d_in[15];
    const float* bo      = (const float*)d_in[16];

    float* out  = (float*)d_out;
    float* outh = out + BATCH * UNITS;

    float *px, *pxg, *pq, *prec, *psc, *pat, *ppar, *pcv, *pz, *prh, *ph, *pgp;
    uint32_t *pwaq, *pctx8;
    void* tmp;
    cudaGetSymbolAddress(&tmp, g_x);         px   = (float*)tmp;
    cudaGetSymbolAddress(&tmp, g_xg);        pxg  = (float*)tmp;
    cudaGetSymbolAddress(&tmp, g_qplus);     pq   = (float*)tmp;
    cudaGetSymbolAddress(&tmp, g_reczr);     prec = (float*)tmp;
    cudaGetSymbolAddress(&tmp, g_score);     psc  = (float*)tmp;
    cudaGetSymbolAddress(&tmp, g_attn);      pat  = (float*)tmp;
    cudaGetSymbolAddress(&tmp, g_partial);   ppar = (float*)tmp;
    cudaGetSymbolAddress(&tmp, g_ctxvec);    pcv  = (float*)tmp;
    cudaGetSymbolAddress(&tmp, g_z);         pz   = (float*)tmp;
    cudaGetSymbolAddress(&tmp, g_rh);        prh  = (float*)tmp;
    cudaGetSymbolAddress(&tmp, g_h);         ph   = (float*)tmp;
    cudaGetSymbolAddress(&tmp, g_gp);        pgp  = (float*)tmp;
    cudaGetSymbolAddress(&tmp, g_WaQ);       pwaq = (uint32_t*)tmp;
    cudaGetSymbolAddress(&tmp, g_ctx8);      pctx8 = (uint32_t*)tmp;

    // raise dynamic smem limit for the score kernel (72 KB > 48 KB default)
    cudaFuncSetAttribute((const void*)score_fp8_kernel,
                         cudaFuncAttributeMaxDynamicSharedMemorySize, 73728);

    // 1. fused prep: Wa -> B-fragments (64 blocks) + context -> A-fragments
    quant_prep_kernel<<<64 + 16384, 256>>>(Wa, context, pwaq, pctx8);

    // 2. merged: x = inputs@Wi ; qplus = h_tm1@Ua ; reczr = h_tm1@reck[:,:1024]
    gemm64_multi_kernel<<<224, 256>>>(inputs, h_tm1, Wi, Ua, reck, pgp);
    reduce_multi_kernel<<<512, 256>>>(pgp, bi, ba_u, ba_w, px, pq, prec);

    // 3. fp8 fused score GEMM (512 threads, 4 warps/SMSP)
    score_fp8_kernel<<<2048, 512, 73728>>>(pctx8, pwaq, pq, Va, psc);

    // 4. xg = x @ kernel + bias   (KS=8)
    gemm64_kernel<<<dim3(24, 8), 256>>>(px, 512, kern, 1536, 0, pgp, 1536);
    reduce64_kernel<<<dim3(6, 64), 256>>>(pgp, 1536, 8, bias, pxg, 1536);

    // 5. softmax over T
    softmax_kernel<<<BATCH, 256>>>(psc, pat);
    // 6. ctx_vec = sum_t attn * context
    ctx_partial_kernel<<<dim3(BATCH, 16), 128>>>(context, pat, ppar);
    ctx_reduce_kernel<<<BATCH * UNITS / 256, 256>>>(ppar, pcv);
    // 7. cg partials = ctx_vec @ attention_kernel (KS=8) -> consumed inline
    gemm64_kernel<<<dim3(24, 8), 256>>>(pcv, 512, attk, 1536, 0, pgp, 1536);
    // 8. z, r gates (sum cg partials inline)
    gate_kernel<<<BATCH * UNITS / 256, 256>>>(pgp, pxg, prec, h_tm1, pz, prh);
    // 9. rec_h partials (disjoint region) + h epilogue (sums rec_h + cg_h)
    gemm64_kernel<<<dim3(8, 8), 256>>>(prh, 512, reck, 1536, 1024, pgp + GP_H, 512);
    hfinal_reduce_kernel<<<dim3(2, 64), 256>>>(pgp, pxg, pz, h_tm1, ph, outh);
    // 10. out = h @ Wo + bo (KS=8)
    gemm64_kernel<<<dim3(8, 8), 256>>>(ph, 512, Wo, 512, 0, pgp, 512);
    reduce64_kernel<<<dim3(2, 64), 256>>>(pgp, 512, 8, bo, out, 512);

    (void)in_sizes; (void)n_in; (void)out_size;
}